// round 17
// baseline (speedup 1.0000x reference)
#include <cuda_runtime.h>

// EfConv: out[n, k*64+o] = b[o] + sum_{e: dst[e]==n} edge_feat[e,k] * z[src[e], o]
// where z = node_feat @ W^T.
//
// Pipeline (multi-stream fork/join inside graph capture):
//   main stream : hist(+rank, 1 edge/thr) -> scan -> build(atomic-free)
//                 -> [join] -> gather
//   side stream : z_kernel (GEMM) concurrent with hist+scan+build
//
// Rank trick: hist records rank[e] = atomicAdd(&counts[dst[e]],1); build
// computes pos = offsets[dst[e]] + rank[e] with NO atomic.
// hist uses ONE edge per thread: the atomic->rank-store chain is latency
// bound, and thread count (not per-thread MLP) covers it (measured lesson
// from build: 25.8us @1/thr vs 34.9us @8/thr on the same structure).

#define MAX_N 50000
#define MAX_E 800000

__device__ float g_z[MAX_N * 64];
__device__ int   g_counts[MAX_N];
__device__ int   g_offsets[MAX_N + 1];
__device__ int   g_rank[MAX_E];          // per-edge rank within its dst bucket
__device__ int   g_srcs[MAX_E];          // src<<8 (byte offset of z row)
__device__ float g_efs[(size_t)MAX_E * 8];

// ---------------------------------------------------------------------------
__device__ __forceinline__ void ffma2(unsigned long long& d,
                                      unsigned long long a,
                                      unsigned long long b) {
    asm("fma.rn.f32x2 %0, %1, %2, %0;" : "+l"(d) : "l"(a), "l"(b));
}
__device__ __forceinline__ unsigned long long dupf(float v) {
    unsigned long long r;
    asm("mov.b64 %0, {%1, %1};" : "=l"(r) : "r"(__float_as_uint(v)));
    return r;
}
__device__ __forceinline__ float2 unpack2(unsigned long long v) {
    unsigned int lo, hi;
    asm("mov.b64 {%0, %1}, %2;" : "=r"(lo), "=r"(hi) : "l"(v));
    return make_float2(__uint_as_float(lo), __uint_as_float(hi));
}

// ---------------------------------------------------------------------------
// z = nf @ W^T, 64 nodes/block, thread = 4 nodes x 2 out-pairs (f32x2).
// ---------------------------------------------------------------------------
__global__ __launch_bounds__(256)
void z_kernel(const float* __restrict__ nf,
              const float* __restrict__ W, int N) {
    __shared__ float Ws[64 * 68];    // Ws[i*68+o] = W[o*64+i]
    __shared__ float nfs[64 * 64];
    int tid = threadIdx.x;

#pragma unroll
    for (int it = 0; it < 16; ++it) {
        int idx = it * 256 + tid;            // idx = o*64 + i
        int o = idx >> 6, i = idx & 63;
        Ws[i * 68 + o] = W[idx];
    }

    int nb = blockIdx.x * 64;
#pragma unroll
    for (int it = 0; it < 16; ++it) {
        int idx = it * 256 + tid;
        int n = nb + (idx >> 6);
        nfs[idx] = (n < N) ? nf[(size_t)n * 64 + (idx & 63)] : 0.0f;
    }
    __syncthreads();

    int ng = tid >> 4;        // node group 0..15
    int ow = tid & 15;        // out quad 0..15
    unsigned long long accp[4][2];
#pragma unroll
    for (int j = 0; j < 4; ++j) { accp[j][0] = 0ull; accp[j][1] = 0ull; }

#pragma unroll 4
    for (int i = 0; i < 64; ++i) {
        ulonglong2 wp = *(const ulonglong2*)(Ws + i * 68 + ow * 4);
        unsigned long long a0 = dupf(nfs[(ng * 4 + 0) * 64 + i]);
        unsigned long long a1 = dupf(nfs[(ng * 4 + 1) * 64 + i]);
        unsigned long long a2 = dupf(nfs[(ng * 4 + 2) * 64 + i]);
        unsigned long long a3 = dupf(nfs[(ng * 4 + 3) * 64 + i]);
        ffma2(accp[0][0], wp.x, a0);  ffma2(accp[0][1], wp.y, a0);
        ffma2(accp[1][0], wp.x, a1);  ffma2(accp[1][1], wp.y, a1);
        ffma2(accp[2][0], wp.x, a2);  ffma2(accp[2][1], wp.y, a2);
        ffma2(accp[3][0], wp.x, a3);  ffma2(accp[3][1], wp.y, a3);
    }

#pragma unroll
    for (int j = 0; j < 4; ++j) {
        int n = nb + ng * 4 + j;
        if (n < N)
            *(ulonglong2*)(g_z + (size_t)n * 64 + ow * 4) =
                make_ulonglong2(accp[j][0], accp[j][1]);
    }
}

// ---------------------------------------------------------------------------
// Histogram + rank recording, ONE edge per thread (max latency cover).
// ---------------------------------------------------------------------------
__global__ __launch_bounds__(256)
void hist_kernel(const int* __restrict__ dst, int E) {
    int e = blockIdx.x * 256 + threadIdx.x;
    if (e < E)
        g_rank[e] = atomicAdd(&g_counts[dst[e]], 1);
}

// ---------------------------------------------------------------------------
__global__ __launch_bounds__(1024)
void scan_kernel(int N) {
    extern __shared__ int ss[];
    int* s     = ss;          // [N]
    int* wsum  = ss + N;      // [32]
    int t    = threadIdx.x;
    int lane = t & 31;
    int wid  = t >> 5;
    int C = (N + 1023) >> 10;

    for (int i = t; i < N; i += 1024) {
        s[i] = g_counts[i];
        g_counts[i] = 0;
    }
    __syncthreads();

    int base = t * C;
    int sum = 0;
    for (int i = 0; i < C; ++i) {
        int n = base + i;
        if (n < N) sum += s[n];
    }

    int v = sum;
#pragma unroll
    for (int d = 1; d < 32; d <<= 1) {
        int u = __shfl_up_sync(0xffffffffu, v, d);
        if (lane >= d) v += u;
    }
    if (lane == 31) wsum[wid] = v;
    __syncthreads();

    if (wid == 0) {
        int wv = wsum[lane];
#pragma unroll
        for (int d = 1; d < 32; d <<= 1) {
            int u = __shfl_up_sync(0xffffffffu, wv, d);
            if (lane >= d) wv += u;
        }
        wsum[lane] = wv;
    }
    __syncthreads();

    int excl = v - sum + (wid > 0 ? wsum[wid - 1] : 0);
    int total = wsum[31];

    int run = excl;
    for (int i = 0; i < C; ++i) {
        int n = base + i;
        if (n < N) {
            int c = s[n];
            s[n] = run;
            run += c;
        }
    }
    __syncthreads();

    for (int i = t; i < N; i += 1024)
        g_offsets[i] = s[i];
    if (t == 0) g_offsets[N] = total;
}

// ---------------------------------------------------------------------------
// Atomic-free scatter: pos = offsets[dst[e]] + rank[e]. One edge per thread.
// ---------------------------------------------------------------------------
__global__ __launch_bounds__(256)
void build_kernel(const int* __restrict__ dst,
                  const int* __restrict__ src,
                  const float* __restrict__ ef, int E) {
    int e = blockIdx.x * 256 + threadIdx.x;
    if (e < E) {
        int d = dst[e];
        int r = g_rank[e];
        int s = src[e];
        const float4* p = (const float4*)(ef + (size_t)e * 8);
        float4 a = p[0];
        float4 c = p[1];
        int pos = g_offsets[d] + r;
        g_srcs[pos] = s << 8;
        float4* q = (float4*)(g_efs + (size_t)pos * 8);
        q[0] = a;
        q[1] = c;
    }
}

// ---------------------------------------------------------------------------
// Warp per node (R8-best). acc[kp] = (out[2kp][c0], out[2kp+1][c0]) packed
// f32x2, acc[4+kp] for c1, (c0,c1)=(2*lane,2*lane+1). Per 32-edge batch:
// lane-parallel resolve into conflict-free smem; inner loop over 4-edge
// groups with z loads pipelined one group ahead.
// ---------------------------------------------------------------------------
__global__ __launch_bounds__(256)
void gather_kernel(const float* __restrict__ bias,
                   float* __restrict__ out, int N) {
    __shared__ __align__(16) float4 sA[8][32];
    __shared__ __align__(16) float4 sB[8][32];
    __shared__ __align__(16) int sOf[8][32];
    int wblk = threadIdx.x >> 5;
    int w    = (blockIdx.x * blockDim.x + threadIdx.x) >> 5;
    int lane = threadIdx.x & 31;
    if (w >= N) return;

    int start = g_offsets[w];
    int cnt   = g_offsets[w + 1] - start;

    float2 bv = ((const float2*)bias)[lane];
    unsigned long long acc[8];
#pragma unroll
    for (int kp = 0; kp < 4; ++kp) {
        acc[kp]     = dupf(bv.x);
        acc[4 + kp] = dupf(bv.y);
    }

    const char* zl = (const char*)g_z + lane * 8;

    for (int base = 0; base < cnt; base += 32) {
        int m = min(32, cnt - base);
        int idx = start + base + lane;
        int off = 0;
        float4 ea = make_float4(0.f, 0.f, 0.f, 0.f);
        float4 eb = make_float4(0.f, 0.f, 0.f, 0.f);
        if (lane < m) {
            off = g_srcs[idx];
            const float4* p = (const float4*)(g_efs + (size_t)idx * 8);
            ea = p[0];
            eb = p[1];
        }
        sOf[wblk][lane] = off;
        sA[wblk][lane] = ea;
        sB[wblk][lane] = eb;
        __syncwarp();

        int groups = (m + 3) >> 2;
        int last = groups - 1;

        int4 o4 = *(const int4*)&sOf[wblk][0];
        float2 z0 = *(const float2*)(zl + o4.x);
        float2 z1 = *(const float2*)(zl + o4.y);
        float2 z2 = *(const float2*)(zl + o4.z);
        float2 z3 = *(const float2*)(zl + o4.w);

        for (int g = 0; g < groups; ++g) {
            int gn = (g < last) ? g + 1 : last;
            int4 o4n = *(const int4*)&sOf[wblk][gn * 4];
            float2 y0 = *(const float2*)(zl + o4n.x);
            float2 y1 = *(const float2*)(zl + o4n.y);
            float2 y2 = *(const float2*)(zl + o4n.z);
            float2 y3 = *(const float2*)(zl + o4n.w);

#pragma unroll
            for (int j = 0; j < 4; ++j) {
                float2 zj = (j == 0) ? z0 : (j == 1) ? z1 : (j == 2) ? z2 : z3;
                int e = g * 4 + j;
                ulonglong2 eA = *(const ulonglong2*)&sA[wblk][e];
                ulonglong2 eB = *(const ulonglong2*)&sB[wblk][e];
                unsigned long long zx = dupf(zj.x);
                unsigned long long zy = dupf(zj.y);
                ffma2(acc[0], eA.x, zx);  ffma2(acc[4], eA.x, zy);
                ffma2(acc[1], eA.y, zx);  ffma2(acc[5], eA.y, zy);
                ffma2(acc[2], eB.x, zx);  ffma2(acc[6], eB.x, zy);
                ffma2(acc[3], eB.y, zx);  ffma2(acc[7], eB.y, zy);
            }
            z0 = y0; z1 = y1; z2 = y2; z3 = y3;
        }
        __syncwarp();
    }

    float* op = out + (size_t)w * 512 + 2 * lane;
#pragma unroll
    for (int kp = 0; kp < 4; ++kp) {
        float2 lo = unpack2(acc[kp]);
        float2 hi = unpack2(acc[4 + kp]);
        *(float2*)(op + (2 * kp) * 64)     = make_float2(lo.x, hi.x);
        *(float2*)(op + (2 * kp + 1) * 64) = make_float2(lo.y, hi.y);
    }
}

// ---------------------------------------------------------------------------
extern "C" void kernel_launch(void* const* d_in, const int* in_sizes, int n_in,
                              void* d_out, int out_size) {
    const float* node_feat = (const float*)d_in[0];
    const float* edge_feat = (const float*)d_in[1];
    const float* W         = (const float*)d_in[2];
    const float* b         = (const float*)d_in[3];
    const int*   src       = (const int*)d_in[4];
    const int*   dst       = (const int*)d_in[5];
    float*       out       = (float*)d_out;

    int N = in_sizes[0] / 64;
    int E = in_sizes[4];

    // one-time infra (no device memory): side stream + fork/join events
    static cudaStream_t s_side = nullptr;
    static cudaEvent_t  ev_fork = nullptr, ev_join = nullptr;
    if (s_side == nullptr) {
        if (cudaStreamCreateWithFlags(&s_side, cudaStreamNonBlocking)
                != cudaSuccess) s_side = nullptr;
        if (s_side) {
            cudaEventCreateWithFlags(&ev_fork, cudaEventDisableTiming);
            cudaEventCreateWithFlags(&ev_join, cudaEventDisableTiming);
        }
    }

    size_t scan_smem = (size_t)(N + 32) * sizeof(int);
    cudaFuncSetAttribute(scan_kernel,
                         cudaFuncAttributeMaxDynamicSharedMemorySize,
                         (int)scan_smem);

    int zb = (N + 63) / 64;

    if (s_side) {
        // fork: z-GEMM on side stream, overlapped with CSR construction
        cudaEventRecord(ev_fork, 0);
        cudaStreamWaitEvent(s_side, ev_fork, 0);
        z_kernel<<<zb, 256, 0, s_side>>>(node_feat, W, N);
        cudaEventRecord(ev_join, s_side);

        hist_kernel<<<(E + 255) / 256, 256>>>(dst, E);
        scan_kernel<<<1, 1024, scan_smem>>>(N);
        build_kernel<<<(E + 255) / 256, 256>>>(dst, src, edge_feat, E);

        cudaStreamWaitEvent(0, ev_join, 0);   // join before gather (needs z)
        gather_kernel<<<(N * 32 + 255) / 256, 256>>>(b, out, N);
    } else {
        // fallback: sequential
        z_kernel<<<zb, 256>>>(node_feat, W, N);
        hist_kernel<<<(E + 255) / 256, 256>>>(dst, E);
        scan_kernel<<<1, 1024, scan_smem>>>(N);
        build_kernel<<<(E + 255) / 256, 256>>>(dst, src, edge_feat, E);
        gather_kernel<<<(N * 32 + 255) / 256, 256>>>(b, out, N);
    }
}